// round 3
// baseline (speedup 1.0000x reference)
#include <cuda_runtime.h>

#define BN 256
#define DN 768
#define TN 128
#define TWO_C 2.0e-5f

// Scratch (allocation-free rule: __device__ globals)
__device__ float g_M[(size_t)BN * TN * TN];  // per-batch Gram, 16.8 MB
__device__ float g_s[BN * TN];               // per-batch solve vector

// ---------------------------------------------------------------------------
// Woodbury identity: A = I_D + 2C * X X^T  (X: [D=768, T=128]) gives
//   w = A^{-1} (2C X y) = 2C * X * (I_T + 2C * X^T X)^{-1} y
// so we only ever need the SMALL (128x128) Gram M = X^T X per batch.
//
// Kernel 1: per-batch Gram. One CTA per batch, 256 threads, 128x128 output
// tile, 8x8 per thread, k-tile = 16 rows of X staged via shared. FFMA-bound.
// ---------------------------------------------------------------------------
__global__ __launch_bounds__(256) void gram_kernel(const float* __restrict__ X) {
    const int b = blockIdx.x;
    const float* __restrict__ Xb = X + (size_t)b * DN * TN;
    __shared__ float xs[16 * TN];  // 16 rows x 128 cols = 8 KB
    const int tid = threadIdx.x;
    const int tx = tid & 15;   // 16 col-tiles
    const int ty = tid >> 4;   // 16 row-tiles

    float acc[8][8];
#pragma unroll
    for (int i = 0; i < 8; ++i)
#pragma unroll
        for (int j = 0; j < 8; ++j) acc[i][j] = 0.f;

    for (int k0 = 0; k0 < DN; k0 += 16) {
        // rows k0..k0+15 are contiguous (row stride = TN = 128): 2048 floats
        const float4* src = reinterpret_cast<const float4*>(Xb + (size_t)k0 * TN);
        float4* dst = reinterpret_cast<float4*>(xs);
        dst[tid]       = src[tid];
        dst[tid + 256] = src[tid + 256];
        __syncthreads();
#pragma unroll
        for (int k = 0; k < 16; ++k) {
            const float4* row = reinterpret_cast<const float4*>(xs + k * TN);
            float4 a0 = row[ty * 2 + 0];
            float4 a1 = row[ty * 2 + 1];
            float4 b0 = row[tx * 2 + 0];
            float4 b1 = row[tx * 2 + 1];
            float a[8] = {a0.x, a0.y, a0.z, a0.w, a1.x, a1.y, a1.z, a1.w};
            float c[8] = {b0.x, b0.y, b0.z, b0.w, b1.x, b1.y, b1.z, b1.w};
#pragma unroll
            for (int i = 0; i < 8; ++i)
#pragma unroll
                for (int j = 0; j < 8; ++j)
                    acc[i][j] = fmaf(a[i], c[j], acc[i][j]);
        }
        __syncthreads();
    }

    float* Mb = g_M + (size_t)b * TN * TN;
#pragma unroll
    for (int i = 0; i < 8; ++i) {
        float4* outrow = reinterpret_cast<float4*>(Mb + (size_t)(ty * 8 + i) * TN + tx * 8);
        outrow[0] = make_float4(acc[i][0], acc[i][1], acc[i][2], acc[i][3]);
        outrow[1] = make_float4(acc[i][4], acc[i][5], acc[i][6], acc[i][7]);
    }
}

// ---------------------------------------------------------------------------
// Kernel 2: solve (I + 2C*M) s = y,  y = [1..128], via fixed point
//   s <- y - 2C * (M s)     rho(2C*M) ~ 2e-5 * sigma_max(X)^2 ~ 0.03
// 12 iterations -> error ~0.03^12 ~ 5e-19 << fp32 eps.
// Thread t owns row t of M (512 B), re-read from global each iteration:
// per-CTA working set = 64 KB, L1-resident after iteration 0. No dynamic
// smem, no cudaFuncSetAttribute.
// ---------------------------------------------------------------------------
__global__ __launch_bounds__(128) void solve_kernel() {
    __shared__ float s[TN];
    const int b = blockIdx.x;
    const int t = threadIdx.x;
    const float* __restrict__ Mrow = g_M + ((size_t)b * TN + t) * TN;

    const float yt = (float)(t + 1);
    s[t] = yt;
    __syncthreads();

    for (int it = 0; it < 12; ++it) {
        float dot = 0.f;
#pragma unroll
        for (int u = 0; u < TN; u += 4) {
            const float4 m = __ldg(reinterpret_cast<const float4*>(Mrow + u));
            dot = fmaf(m.x, s[u + 0],
                  fmaf(m.y, s[u + 1],
                  fmaf(m.z, s[u + 2],
                  fmaf(m.w, s[u + 3], dot))));
        }
        const float sn = yt - TWO_C * dot;
        __syncthreads();
        s[t] = sn;
        __syncthreads();
    }
    g_s[b * TN + t] = s[t];
}

// ---------------------------------------------------------------------------
// Kernel 3: w[b,d] = 2C * sum_t X[b,d,t] * s[b,t]
// One warp per output row: lane loads float4 (coalesced 512 B per row),
// warp shuffle reduce. Memory-bound streaming pass over X.
// ---------------------------------------------------------------------------
__global__ __launch_bounds__(256) void out_kernel(const float* __restrict__ X,
                                                  float* __restrict__ W) {
    const int b = blockIdx.y;
    __shared__ float ss[TN];
    if (threadIdx.x < TN) ss[threadIdx.x] = g_s[b * TN + threadIdx.x];
    __syncthreads();

    const int warp = threadIdx.x >> 5;
    const int lane = threadIdx.x & 31;
    const int d = blockIdx.x * 8 + warp;

    const float4 v  = reinterpret_cast<const float4*>(X + ((size_t)b * DN + d) * TN)[lane];
    const float4 sv = reinterpret_cast<const float4*>(ss)[lane];
    float acc = v.x * sv.x + v.y * sv.y + v.z * sv.z + v.w * sv.w;
#pragma unroll
    for (int o = 16; o; o >>= 1) acc += __shfl_xor_sync(0xffffffffu, acc, o);
    if (lane == 0) W[(size_t)b * DN + d] = TWO_C * acc;
}

// ---------------------------------------------------------------------------
extern "C" void kernel_launch(void* const* d_in, const int* in_sizes, int n_in,
                              void* d_out, int out_size) {
    (void)in_sizes; (void)n_in; (void)out_size;
    const float* X = (const float*)d_in[0];
    float* W = (float*)d_out;

    gram_kernel<<<BN, 256>>>(X);
    solve_kernel<<<BN, 128>>>();
    out_kernel<<<dim3(DN / 8, BN), 256>>>(X, W);
}

// round 6
// speedup vs baseline: 5.5684x; 5.5684x over previous
#include <cuda_runtime.h>
#include <cuda_bf16.h>
#include <cstdint>

#define BN 256
#define DN 768
#define TN 128
#define KC 32                 /* d-rows staged per chunk            */
#define NCH (DN / KC)         /* 24 chunks                          */
#define SROW 136              /* bf16 elems per staged row (128+8)  */
#define TWO_C 2.0e-5f
#define NIT 6                 /* fixed-point iterations             */

__device__ __forceinline__ uint32_t smem_u32(const void* p) {
    uint32_t a;
    asm("{ .reg .u64 t; cvta.to.shared.u64 t, %1; cvt.u32.u64 %0, t; }" : "=r"(a) : "l"(p));
    return a;
}
__device__ __forceinline__ void ldsm4t(uint32_t addr, uint32_t r[4]) {
    asm volatile("ldmatrix.sync.aligned.m8n8.x4.trans.shared.b16 {%0,%1,%2,%3}, [%4];"
                 : "=r"(r[0]), "=r"(r[1]), "=r"(r[2]), "=r"(r[3]) : "r"(addr));
}
__device__ __forceinline__ void mma16816(float c[4], const uint32_t a[4],
                                         uint32_t b0, uint32_t b1) {
    asm volatile("mma.sync.aligned.m16n8k16.row.col.f32.bf16.bf16.f32 "
                 "{%0,%1,%2,%3}, {%4,%5,%6,%7}, {%8,%9}, {%0,%1,%2,%3};"
                 : "+f"(c[0]), "+f"(c[1]), "+f"(c[2]), "+f"(c[3])
                 : "r"(a[0]), "r"(a[1]), "r"(a[2]), "r"(a[3]), "r"(b0), "r"(b1));
}

// ---------------------------------------------------------------------------
// One CTA per batch b. X_b : [D=768][T=128] f32 (t contiguous).
// Woodbury: w = 2C * X * (I + 2C X^T X)^{-1} y,  y = 1..128.
//
// Phase 1: M = X^T X via warp-level bf16 HMMA. Staged tile = 32 d-rows of X
//   as bf16 [d][t] (row stride 136). Both operands of the MMA come from the
//   same tile via ldmatrix.trans:
//     A(m=t, k=d) <- stored [k][m]  (trans)
//     B(k=d, n=t) <- stored [k][n]  (trans)
//   Warp grid 4x2: warp (wm,wn) owns M[wm*32 .. +32)[wn*64 .. +64),
//   i.e. 2 m16-tiles x 8 n8-tiles, fp32 acc in registers.
// Phase 2: fixed-point solve with M left distributed in registers.
// Phase 3: w = 2C * X s, fp32 streaming (L2-resident second pass).
// ---------------------------------------------------------------------------
__global__ __launch_bounds__(256, 2) void rankpool_fused(const float* __restrict__ X,
                                                         float* __restrict__ W) {
    __shared__ __align__(16) __nv_bfloat16 stage[2][KC * SROW];  // 2 x 8704 B
    __shared__ float s_sh[TN];
    __shared__ float tmp[2][TN];

    const int b = blockIdx.x;
    const int tid = threadIdx.x;
    const int wid = tid >> 5;
    const int lane = tid & 31;
    const int g = lane >> 2, tig = lane & 3;
    const int wm = wid & 3, wn = wid >> 2;
    const int li = lane & 7, lb3 = (lane >> 3) & 1, lb4 = lane >> 4;

    const float4* __restrict__ Xb4 =
        reinterpret_cast<const float4*>(X + (size_t)b * DN * TN);

    float acc[2][8][4];
#pragma unroll
    for (int mt = 0; mt < 2; ++mt)
#pragma unroll
        for (int nt = 0; nt < 8; ++nt)
#pragma unroll
            for (int c = 0; c < 4; ++c) acc[mt][nt][c] = 0.f;

    // per-lane ldmatrix byte offsets within a buffer (ks adds 16*SROW*2)
    // A tile mt: lanes 0-7 -> rows k0..7 col m0 ; 8-15 -> col m0+8 ;
    //            16-23 -> rows k8..15 col m0 ; 24-31 -> col m0+8
    uint32_t aoff[2], boff[4];
#pragma unroll
    for (int mt = 0; mt < 2; ++mt)
        aoff[mt] = (uint32_t)(((lb4 * 8 + li) * SROW + wm * 32 + mt * 16 + lb3 * 8) * 2);
    // B pair j covers n-tiles 2j, 2j+1:
    // lanes 0-7 -> rows k0..7 col nA ; 8-15 -> rows k8..15 col nA ;
    // 16-23 -> rows k0..7 col nB ; 24-31 -> rows k8..15 col nB
#pragma unroll
    for (int j = 0; j < 4; ++j)
        boff[j] = (uint32_t)(((lb3 * 8 + li) * SROW + wn * 64 + j * 16 + lb4 * 8) * 2);

    const uint32_t buf_addr[2] = {smem_u32(&stage[0][0]), smem_u32(&stage[1][0])};

    // ---------------- Phase 1: Gram ----------------
    float4 pf[4];
#pragma unroll
    for (int i = 0; i < 4; ++i) pf[i] = Xb4[tid + i * 256];

    for (int c = 0; c < NCH; ++c) {
        const int bf = c & 1;
        __syncthreads();  // previous compute on this buffer finished
        // store prefetched chunk as bf16 [d][t], row stride SROW
#pragma unroll
        for (int i = 0; i < 4; ++i) {
            const int f = tid + i * 256;          // f4 index within chunk
            const int d = f >> 5;                 // 32 float4 per d-row
            const int t0 = (f & 31) * 4;
            __nv_bfloat162 p0 = __floats2bfloat162_rn(pf[i].x, pf[i].y);
            __nv_bfloat162 p1 = __floats2bfloat162_rn(pf[i].z, pf[i].w);
            *reinterpret_cast<__nv_bfloat162*>(&stage[bf][d * SROW + t0]) = p0;
            *reinterpret_cast<__nv_bfloat162*>(&stage[bf][d * SROW + t0 + 2]) = p1;
        }
        if (c + 1 < NCH) {
            const int base = (c + 1) * (KC * TN / 4);
#pragma unroll
            for (int i = 0; i < 4; ++i) pf[i] = Xb4[base + tid + i * 256];
        }
        __syncthreads();  // staging visible

#pragma unroll
        for (int ks = 0; ks < 2; ++ks) {   // two K=16 steps per 32-row chunk
            const uint32_t kbase = buf_addr[bf] + (uint32_t)(ks * 16 * SROW * 2);
            uint32_t a[2][4], bb[4][4];
            ldsm4t(kbase + aoff[0], a[0]);
            ldsm4t(kbase + aoff[1], a[1]);
#pragma unroll
            for (int j = 0; j < 4; ++j) ldsm4t(kbase + boff[j], bb[j]);
#pragma unroll
            for (int mt = 0; mt < 2; ++mt)
#pragma unroll
                for (int j = 0; j < 4; ++j) {
                    mma16816(acc[mt][2 * j + 0], a[mt], bb[j][0], bb[j][1]);
                    mma16816(acc[mt][2 * j + 1], a[mt], bb[j][2], bb[j][3]);
                }
        }
    }

    // ---------------- Phase 2: fixed-point solve ----------------
    // thread's M elements: m(mt,h) = wm*32 + mt*16 + h*8 + g
    //                      n(nt,q) = wn*64 + nt*8  + 2*tig + q
    if (tid < TN) s_sh[tid] = (float)(tid + 1);
    __syncthreads();

    for (int it = 0; it < NIT; ++it) {
        float p[2][2] = {{0.f, 0.f}, {0.f, 0.f}};
#pragma unroll
        for (int nt = 0; nt < 8; ++nt) {
            const float2 sv =
                *reinterpret_cast<const float2*>(&s_sh[wn * 64 + nt * 8 + 2 * tig]);
#pragma unroll
            for (int mt = 0; mt < 2; ++mt) {
                p[mt][0] = fmaf(acc[mt][nt][0], sv.x, fmaf(acc[mt][nt][1], sv.y, p[mt][0]));
                p[mt][1] = fmaf(acc[mt][nt][2], sv.x, fmaf(acc[mt][nt][3], sv.y, p[mt][1]));
            }
        }
#pragma unroll
        for (int mt = 0; mt < 2; ++mt)
#pragma unroll
            for (int h = 0; h < 2; ++h) {
                p[mt][h] += __shfl_xor_sync(0xffffffffu, p[mt][h], 1);
                p[mt][h] += __shfl_xor_sync(0xffffffffu, p[mt][h], 2);
            }
        if (tig == 0) {
#pragma unroll
            for (int mt = 0; mt < 2; ++mt)
#pragma unroll
                for (int h = 0; h < 2; ++h)
                    tmp[wn][wm * 32 + mt * 16 + h * 8 + g] = p[mt][h];
        }
        __syncthreads();   // tmp complete; all s_sh reads done
        if (tid < TN) {
            const float sn = (float)(tid + 1) - TWO_C * (tmp[0][tid] + tmp[1][tid]);
            s_sh[tid] = sn;  // safe: every reader re-syncs below before reading
        }
        __syncthreads();
    }

    // ---------------- Phase 3: epilogue w = 2C * X s ----------------
    const float4 sv4 = reinterpret_cast<const float4*>(s_sh)[lane];
    float* Wb = W + (size_t)b * DN;
#pragma unroll 4
    for (int r = 0; r < DN / 8; ++r) {
        const int d = r * 8 + wid;
        const float4 v = Xb4[d * 32 + lane];
        float a = v.x * sv4.x + v.y * sv4.y + v.z * sv4.z + v.w * sv4.w;
#pragma unroll
        for (int o = 16; o; o >>= 1) a += __shfl_xor_sync(0xffffffffu, a, o);
        if (lane == 0) Wb[d] = TWO_C * a;
    }
}

// ---------------------------------------------------------------------------
extern "C" void kernel_launch(void* const* d_in, const int* in_sizes, int n_in,
                              void* d_out, int out_size) {
    (void)in_sizes; (void)n_in; (void)out_size;
    rankpool_fused<<<BN, 256>>>((const float*)d_in[0], (float*)d_out);
}

// round 7
// speedup vs baseline: 6.1234x; 1.0997x over previous
#include <cuda_runtime.h>
#include <cuda_bf16.h>
#include <cstdint>

#define BN 256
#define DN 768
#define TN 128
#define NSUB 48               /* 16-row f32 sub-chunks              */
#define SROW 136              /* bf16 elems per staged row (128+8)  */
#define TWO_C 2.0e-5f
#define NIT 6                 /* fixed-point iterations             */

__device__ __forceinline__ uint32_t smem_u32(const void* p) {
    uint32_t a;
    asm("{ .reg .u64 t; cvta.to.shared.u64 t, %1; cvt.u32.u64 %0, t; }" : "=r"(a) : "l"(p));
    return a;
}
__device__ __forceinline__ void cp16(uint32_t dst, const void* src) {
    asm volatile("cp.async.cg.shared.global [%0], [%1], 16;" :: "r"(dst), "l"(src));
}
#define CP_COMMIT() asm volatile("cp.async.commit_group;" ::: "memory")
#define CP_WAIT2()  asm volatile("cp.async.wait_group 2;" ::: "memory")
__device__ __forceinline__ void ldsm4t(uint32_t addr, uint32_t r[4]) {
    asm volatile("ldmatrix.sync.aligned.m8n8.x4.trans.shared.b16 {%0,%1,%2,%3}, [%4];"
                 : "=r"(r[0]), "=r"(r[1]), "=r"(r[2]), "=r"(r[3]) : "r"(addr));
}
__device__ __forceinline__ void mma16816(float c[4], const uint32_t a[4],
                                         uint32_t b0, uint32_t b1) {
    asm volatile("mma.sync.aligned.m16n8k16.row.col.f32.bf16.bf16.f32 "
                 "{%0,%1,%2,%3}, {%4,%5,%6,%7}, {%8,%9}, {%0,%1,%2,%3};"
                 : "+f"(c[0]), "+f"(c[1]), "+f"(c[2]), "+f"(c[3])
                 : "r"(a[0]), "r"(a[1]), "r"(a[2]), "r"(a[3]), "r"(b0), "r"(b1));
}

// ---------------------------------------------------------------------------
// One CTA per batch b. X_b : [D=768][T=128] f32 (t contiguous).
// Woodbury: w = 2C * X * (I + 2C X^T X)^{-1} y,  y = 1..128.
//
// Phase 1: M = X^T X via bf16 HMMA.
//   - 4-deep cp.async ring of raw f32 16-row sub-chunks (8 KB each). Each
//     thread copies and later converts ITS OWN 32 B -> no barrier on the ring.
//   - f32 -> bf16 conversion writes a single 32-row staging tile [d][t],
//     row stride 136; ldmatrix.trans serves both A (=X^T) and B (=X).
//   - Warp grid 4x2: warp (wm,wn) owns M[wm*32..+32)[wn*64..+64), fp32 acc.
// Phase 2: fixed-point solve (I + 2C M) s = y with M left in registers.
// Phase 3: w = 2C * X s; 8 lanes per row, 4 rows per warp per iteration,
//   s in registers -> 3 shfls per 4 rows, fully coalesced 128B-line loads.
// ---------------------------------------------------------------------------
__global__ __launch_bounds__(256, 2) void rankpool_fused(const float* __restrict__ X,
                                                         float* __restrict__ W) {
    __shared__ __align__(16) float4 ring[4][512];            // 32 KB f32 ring
    __shared__ __align__(16) __nv_bfloat16 stg[32 * SROW];   // 8704 B bf16 tile
    __shared__ float s_sh[TN];
    __shared__ float tmp[2][TN];

    const int b = blockIdx.x;
    const int tid = threadIdx.x;
    const int wid = tid >> 5;
    const int lane = tid & 31;
    const int g = lane >> 2, tig = lane & 3;
    const int wm = wid & 3, wn = wid >> 2;
    const int li = lane & 7, lb3 = (lane >> 3) & 1, lb4 = lane >> 4;

    const float4* __restrict__ Xb4 =
        reinterpret_cast<const float4*>(X + (size_t)b * DN * TN);

    float acc[2][8][4];
#pragma unroll
    for (int mt = 0; mt < 2; ++mt)
#pragma unroll
        for (int nt = 0; nt < 8; ++nt)
#pragma unroll
            for (int c = 0; c < 4; ++c) acc[mt][nt][c] = 0.f;

    // ldmatrix per-lane byte offsets in stg (ks adds 16*SROW*2)
    uint32_t aoff[2], boff[4];
#pragma unroll
    for (int mt = 0; mt < 2; ++mt)
        aoff[mt] = (uint32_t)(((lb4 * 8 + li) * SROW + wm * 32 + mt * 16 + lb3 * 8) * 2);
#pragma unroll
    for (int j = 0; j < 4; ++j)
        boff[j] = (uint32_t)(((lb3 * 8 + li) * SROW + wn * 64 + j * 16 + lb4 * 8) * 2);

    const uint32_t stg_addr = smem_u32(&stg[0]);
    const uint32_t ring_addr = smem_u32(&ring[0][0]);

    // thread-local sub-chunk mapping (same 32 B in copy and convert)
    const int dl0 = tid >> 5;              // 0..7   (f = tid)
    const int dl1 = (tid + 256) >> 5;      // 8..15  (f = tid+256)
    const int t0 = (tid & 31) * 4;

    // ---------------- Phase 1: Gram ----------------
    // prologue: issue subs 0..2
#pragma unroll
    for (int s = 0; s < 3; ++s) {
        const uint32_t dst = ring_addr + (uint32_t)(s * 512 + tid) * 16u;
        cp16(dst, Xb4 + s * 512 + tid);
        cp16(dst + 256 * 16, Xb4 + s * 512 + tid + 256);
        CP_COMMIT();
    }

    for (int s = 0; s < NSUB; ++s) {
        CP_WAIT2();                         // own sub s data resident
        const float4* st = ring[s & 3];
        const int rbase = (s & 1) * 16;
        {
            const float4 v0 = st[tid];
            const float4 v1 = st[tid + 256];
            __nv_bfloat162 p0 = __floats2bfloat162_rn(v0.x, v0.y);
            __nv_bfloat162 p1 = __floats2bfloat162_rn(v0.z, v0.w);
            uint2 u0; u0.x = *reinterpret_cast<uint32_t*>(&p0);
            u0.y = *reinterpret_cast<uint32_t*>(&p1);
            *reinterpret_cast<uint2*>(&stg[(rbase + dl0) * SROW + t0]) = u0;
            __nv_bfloat162 q0 = __floats2bfloat162_rn(v1.x, v1.y);
            __nv_bfloat162 q1 = __floats2bfloat162_rn(v1.z, v1.w);
            uint2 u1; u1.x = *reinterpret_cast<uint32_t*>(&q0);
            u1.y = *reinterpret_cast<uint32_t*>(&q1);
            *reinterpret_cast<uint2*>(&stg[(rbase + dl1) * SROW + t0]) = u1;
        }
        if (s + 3 < NSUB) {                 // issue sub s+3 into stage (s-1)%4
            const uint32_t dst = ring_addr + (uint32_t)(((s + 3) & 3) * 512 + tid) * 16u;
            cp16(dst, Xb4 + (s + 3) * 512 + tid);
            cp16(dst + 256 * 16, Xb4 + (s + 3) * 512 + tid + 256);
        }
        CP_COMMIT();                        // empty group at tail keeps count

        if (s & 1) {
            __syncthreads();                // 32-row bf16 tile visible
#pragma unroll
            for (int ks = 0; ks < 2; ++ks) {
                const uint32_t kbase = stg_addr + (uint32_t)(ks * 16 * SROW * 2);
                uint32_t a[2][4], bb[4][4];
                ldsm4t(kbase + aoff[0], a[0]);
                ldsm4t(kbase + aoff[1], a[1]);
#pragma unroll
                for (int j = 0; j < 4; ++j) ldsm4t(kbase + boff[j], bb[j]);
#pragma unroll
                for (int mt = 0; mt < 2; ++mt)
#pragma unroll
                    for (int j = 0; j < 4; ++j) {
                        mma16816(acc[mt][2 * j + 0], a[mt], bb[j][0], bb[j][1]);
                        mma16816(acc[mt][2 * j + 1], a[mt], bb[j][2], bb[j][3]);
                    }
            }
            __syncthreads();                // tile consumed; stg reusable
        }
    }

    // ---------------- Phase 2: fixed-point solve ----------------
    // thread's M elements: m(mt,h) = wm*32 + mt*16 + h*8 + g
    //                      n(nt,q) = wn*64 + nt*8  + 2*tig + q
    if (tid < TN) s_sh[tid] = (float)(tid + 1);
    __syncthreads();

    for (int it = 0; it < NIT; ++it) {
        float p[2][2] = {{0.f, 0.f}, {0.f, 0.f}};
#pragma unroll
        for (int nt = 0; nt < 8; ++nt) {
            const float2 sv =
                *reinterpret_cast<const float2*>(&s_sh[wn * 64 + nt * 8 + 2 * tig]);
#pragma unroll
            for (int mt = 0; mt < 2; ++mt) {
                p[mt][0] = fmaf(acc[mt][nt][0], sv.x, fmaf(acc[mt][nt][1], sv.y, p[mt][0]));
                p[mt][1] = fmaf(acc[mt][nt][2], sv.x, fmaf(acc[mt][nt][3], sv.y, p[mt][1]));
            }
        }
#pragma unroll
        for (int mt = 0; mt < 2; ++mt)
#pragma unroll
            for (int h = 0; h < 2; ++h) {
                p[mt][h] += __shfl_xor_sync(0xffffffffu, p[mt][h], 1);
                p[mt][h] += __shfl_xor_sync(0xffffffffu, p[mt][h], 2);
            }
        if (tig == 0) {
#pragma unroll
            for (int mt = 0; mt < 2; ++mt)
#pragma unroll
                for (int h = 0; h < 2; ++h)
                    tmp[wn][wm * 32 + mt * 16 + h * 8 + g] = p[mt][h];
        }
        __syncthreads();
        if (tid < TN)
            s_sh[tid] = (float)(tid + 1) - TWO_C * (tmp[0][tid] + tmp[1][tid]);
        __syncthreads();
    }

    // ---------------- Phase 3: epilogue w = 2C * X s ----------------
    // warp computes 4 rows/iter; 8 lanes per row; s kept in registers.
    const int li8 = lane & 7, rsub = lane >> 3;
    float4 sr[4];
    {
        const float4* s4 = reinterpret_cast<const float4*>(s_sh);
#pragma unroll
        for (int i = 0; i < 4; ++i) sr[i] = s4[i * 8 + li8];
    }
    float* Wb = W + (size_t)b * DN;
#pragma unroll 2
    for (int r = 0; r < DN / 32; ++r) {
        const int d = r * 32 + wid * 4 + rsub;
        const float4* row = Xb4 + (size_t)d * 32;
        float p0 = 0.f, p1 = 0.f;
#pragma unroll
        for (int i = 0; i < 4; i += 2) {
            const float4 v0 = row[i * 8 + li8];
            const float4 v1 = row[(i + 1) * 8 + li8];
            p0 = fmaf(v0.x, sr[i].x, fmaf(v0.y, sr[i].y,
                 fmaf(v0.z, sr[i].z, fmaf(v0.w, sr[i].w, p0))));
            p1 = fmaf(v1.x, sr[i + 1].x, fmaf(v1.y, sr[i + 1].y,
                 fmaf(v1.z, sr[i + 1].z, fmaf(v1.w, sr[i + 1].w, p1))));
        }
        float a = p0 + p1;
        a += __shfl_xor_sync(0xffffffffu, a, 1);
        a += __shfl_xor_sync(0xffffffffu, a, 2);
        a += __shfl_xor_sync(0xffffffffu, a, 4);
        if (li8 == 0) Wb[d] = TWO_C * a;
    }
}

// ---------------------------------------------------------------------------
extern "C" void kernel_launch(void* const* d_in, const int* in_sizes, int n_in,
                              void* d_out, int out_size) {
    (void)in_sizes; (void)n_in; (void)out_size;
    rankpool_fused<<<BN, 256>>>((const float*)d_in[0], (float*)d_out);
}

// round 8
// speedup vs baseline: 6.4445x; 1.0525x over previous
#include <cuda_runtime.h>
#include <cuda_bf16.h>
#include <cstdint>

#define BN 256
#define DN 768
#define TN 128
#define NCH 24                /* 32-row chunks                      */
#define SROW 136              /* bf16 elems per staged row (128+8)  */
#define TWO_C 2.0e-5f
#define NIT 4                 /* fixed-point iterations             */

__device__ __forceinline__ uint32_t smem_u32(const void* p) {
    uint32_t a;
    asm("{ .reg .u64 t; cvta.to.shared.u64 t, %1; cvt.u32.u64 %0, t; }" : "=r"(a) : "l"(p));
    return a;
}
__device__ __forceinline__ void cp16(uint32_t dst, const void* src) {
    asm volatile("cp.async.cg.shared.global [%0], [%1], 16;" :: "r"(dst), "l"(src));
}
#define CP_COMMIT() asm volatile("cp.async.commit_group;" ::: "memory")
#define CP_WAIT1()  asm volatile("cp.async.wait_group 1;" ::: "memory")
__device__ __forceinline__ void ldsm4t(uint32_t addr, uint32_t r[4]) {
    asm volatile("ldmatrix.sync.aligned.m8n8.x4.trans.shared.b16 {%0,%1,%2,%3}, [%4];"
                 : "=r"(r[0]), "=r"(r[1]), "=r"(r[2]), "=r"(r[3]) : "r"(addr));
}
__device__ __forceinline__ void mma16816(float c[4], const uint32_t a[4],
                                         uint32_t b0, uint32_t b1) {
    asm volatile("mma.sync.aligned.m16n8k16.row.col.f32.bf16.bf16.f32 "
                 "{%0,%1,%2,%3}, {%4,%5,%6,%7}, {%8,%9}, {%0,%1,%2,%3};"
                 : "+f"(c[0]), "+f"(c[1]), "+f"(c[2]), "+f"(c[3])
                 : "r"(a[0]), "r"(a[1]), "r"(a[2]), "r"(a[3]), "r"(b0), "r"(b1));
}

// ---------------------------------------------------------------------------
// One CTA per batch b. X_b : [D=768][T=128] f32. Woodbury:
//   w = 2C * X * (I + 2C X^T X)^{-1} y,  y = 1..128.
//
// Phase 1 (Gram, software-pipelined):
//   per 32-row chunk c:   sync; ldsm+MMA tile c from stg[c&1]   (tensor pipe)
//                         then convert tile c+1 into stg[(c+1)&1]  (L1 pipe)
//   so tensor work drains WHILE the conversion runs. One barrier per chunk.
//   f32 data arrives through a 3-deep cp.async ring of 16-row subs (8 KB);
//   each thread cp's and converts ITS OWN 32 B -> ring needs no barriers.
// Phase 2: fixed-point solve (I + 2C M) s = y, M in registers. 4 iters.
// Phase 3: w = 2C * X s, read in REVERSE chunk order (tail chunks are the
//   most recently streamed -> still L2 resident).
// ---------------------------------------------------------------------------
__global__ __launch_bounds__(256, 2) void rankpool_fused(const float* __restrict__ X,
                                                         float* __restrict__ W) {
    __shared__ __align__(16) float4 ring[3][512];               // 24 KB f32 ring
    __shared__ __align__(16) __nv_bfloat16 stg[2][32 * SROW];   // 17 KB bf16 tiles
    __shared__ float s_sh[TN];
    __shared__ float tmp[2][TN];

    const int b = blockIdx.x;
    const int tid = threadIdx.x;
    const int wid = tid >> 5;
    const int lane = tid & 31;
    const int g = lane >> 2, tig = lane & 3;
    const int wm = wid & 3, wn = wid >> 2;
    const int li = lane & 7, lb3 = (lane >> 3) & 1, lb4 = lane >> 4;

    const float4* __restrict__ Xb4 =
        reinterpret_cast<const float4*>(X + (size_t)b * DN * TN);

    float acc[2][8][4];
#pragma unroll
    for (int mt = 0; mt < 2; ++mt)
#pragma unroll
        for (int nt = 0; nt < 8; ++nt)
#pragma unroll
            for (int c = 0; c < 4; ++c) acc[mt][nt][c] = 0.f;

    // ldmatrix per-lane byte offsets (ks adds 16*SROW*2; buffer adds 32*SROW*2)
    uint32_t aoff[2], boff[4];
#pragma unroll
    for (int mt = 0; mt < 2; ++mt)
        aoff[mt] = (uint32_t)(((lb4 * 8 + li) * SROW + wm * 32 + mt * 16 + lb3 * 8) * 2);
#pragma unroll
    for (int j = 0; j < 4; ++j)
        boff[j] = (uint32_t)(((lb3 * 8 + li) * SROW + wn * 64 + j * 16 + lb4 * 8) * 2);

    const uint32_t stg_addr0 = smem_u32(&stg[0][0]);
    const uint32_t ring_addr = smem_u32(&ring[0][0]);

    const int dl0 = tid >> 5;              // d-row for f = tid       (0..7)
    const int dl1 = (tid + 256) >> 5;      // d-row for f = tid+256   (8..15)
    const int t0 = (tid & 31) * 4;

    // convert one 16-row sub from ring slot -> stg rows rbase..rbase+15
    auto convert_sub = [&](int slot, int buf, int rbase) {
        const float4* st = ring[slot];
        const float4 v0 = st[tid];
        const float4 v1 = st[tid + 256];
        __nv_bfloat162 p0 = __floats2bfloat162_rn(v0.x, v0.y);
        __nv_bfloat162 p1 = __floats2bfloat162_rn(v0.z, v0.w);
        uint2 u0; u0.x = *reinterpret_cast<const uint32_t*>(&p0);
        u0.y = *reinterpret_cast<const uint32_t*>(&p1);
        *reinterpret_cast<uint2*>(&stg[buf][(rbase + dl0) * SROW + t0]) = u0;
        __nv_bfloat162 q0 = __floats2bfloat162_rn(v1.x, v1.y);
        __nv_bfloat162 q1 = __floats2bfloat162_rn(v1.z, v1.w);
        uint2 u1; u1.x = *reinterpret_cast<const uint32_t*>(&q0);
        u1.y = *reinterpret_cast<const uint32_t*>(&q1);
        *reinterpret_cast<uint2*>(&stg[buf][(rbase + dl1) * SROW + t0]) = u1;
    };
    auto issue_sub = [&](int s) {          // 16-row f32 sub s -> ring slot s%3
        const uint32_t dst = ring_addr + (uint32_t)((s % 3) * 512 + tid) * 16u;
        cp16(dst, Xb4 + s * 512 + tid);
        cp16(dst + 256 * 16, Xb4 + s * 512 + tid + 256);
    };

    // ---------------- Phase 1: Gram ----------------
    // prologue: subs 0,1,2 in flight; convert tile 0; issue subs 3,4
#pragma unroll
    for (int s = 0; s < 3; ++s) { issue_sub(s); CP_COMMIT(); }
    CP_WAIT1();                            // subs 0,1 resident
    convert_sub(0, 0, 0);
    convert_sub(1, 0, 16);
    issue_sub(3); CP_COMMIT();
    issue_sub(4); CP_COMMIT();             // pending: subs 2,3,4

    for (int c = 0; c < NCH; ++c) {
        const uint32_t mybuf = stg_addr0 + (uint32_t)((c & 1) * 32 * SROW * 2);
        __syncthreads();   // stg[c&1] visible; stg[(c+1)&1] free (MMA c-1 done)

        // MMA tile c (issue first -> tensor pipe overlaps conversion below)
#pragma unroll
        for (int ks = 0; ks < 2; ++ks) {
            const uint32_t kbase = mybuf + (uint32_t)(ks * 16 * SROW * 2);
            uint32_t a[2][4], bb[4][4];
            ldsm4t(kbase + aoff[0], a[0]);
            ldsm4t(kbase + aoff[1], a[1]);
#pragma unroll
            for (int j = 0; j < 4; ++j) ldsm4t(kbase + boff[j], bb[j]);
#pragma unroll
            for (int mt = 0; mt < 2; ++mt)
#pragma unroll
                for (int j = 0; j < 4; ++j) {
                    mma16816(acc[mt][2 * j + 0], a[mt], bb[j][0], bb[j][1]);
                    mma16816(acc[mt][2 * j + 1], a[mt], bb[j][2], bb[j][3]);
                }
        }

        // convert tile c+1 (subs 2c+2, 2c+3) while MMAs drain
        if (c + 1 < NCH) {
            CP_WAIT1();                    // subs 2c+2, 2c+3 resident
            convert_sub((2 * c + 2) % 3, (c + 1) & 1, 0);
            convert_sub((2 * c + 3) % 3, (c + 1) & 1, 16);
            if (2 * c + 5 < 2 * NCH) issue_sub(2 * c + 5);
            CP_COMMIT();
            if (2 * c + 6 < 2 * NCH) issue_sub(2 * c + 6);
            CP_COMMIT();
        }
    }

    // ---------------- Phase 2: fixed-point solve ----------------
    // thread's M elements: m(mt,h) = wm*32 + mt*16 + h*8 + g
    //                      n(nt,q) = wn*64 + nt*8  + 2*tig + q
    if (tid < TN) s_sh[tid] = (float)(tid + 1);
    __syncthreads();

    for (int it = 0; it < NIT; ++it) {
        float p[2][2] = {{0.f, 0.f}, {0.f, 0.f}};
#pragma unroll
        for (int nt = 0; nt < 8; ++nt) {
            const float2 sv =
                *reinterpret_cast<const float2*>(&s_sh[wn * 64 + nt * 8 + 2 * tig]);
#pragma unroll
            for (int mt = 0; mt < 2; ++mt) {
                p[mt][0] = fmaf(acc[mt][nt][0], sv.x, fmaf(acc[mt][nt][1], sv.y, p[mt][0]));
                p[mt][1] = fmaf(acc[mt][nt][2], sv.x, fmaf(acc[mt][nt][3], sv.y, p[mt][1]));
            }
        }
#pragma unroll
        for (int mt = 0; mt < 2; ++mt)
#pragma unroll
            for (int h = 0; h < 2; ++h) {
                p[mt][h] += __shfl_xor_sync(0xffffffffu, p[mt][h], 1);
                p[mt][h] += __shfl_xor_sync(0xffffffffu, p[mt][h], 2);
            }
        if (tig == 0) {
#pragma unroll
            for (int mt = 0; mt < 2; ++mt)
#pragma unroll
                for (int h = 0; h < 2; ++h)
                    tmp[wn][wm * 32 + mt * 16 + h * 8 + g] = p[mt][h];
        }
        __syncthreads();
        if (tid < TN)
            s_sh[tid] = (float)(tid + 1) - TWO_C * (tmp[0][tid] + tmp[1][tid]);
        __syncthreads();
    }

    // ---------------- Phase 3: epilogue w = 2C * X s (reverse order) -----
    const int li8 = lane & 7, rsub = lane >> 3;
    float4 sr[4];
    {
        const float4* s4 = reinterpret_cast<const float4*>(s_sh);
#pragma unroll
        for (int i = 0; i < 4; ++i) sr[i] = s4[i * 8 + li8];
    }
    float* Wb = W + (size_t)b * DN;
#pragma unroll 2
    for (int r = DN / 32 - 1; r >= 0; --r) {
        const int d = r * 32 + wid * 4 + rsub;
        const float4* row = Xb4 + (size_t)d * 32;
        float p0 = 0.f, p1 = 0.f;
#pragma unroll
        for (int i = 0; i < 4; i += 2) {
            const float4 v0 = row[i * 8 + li8];
            const float4 v1 = row[(i + 1) * 8 + li8];
            p0 = fmaf(v0.x, sr[i].x, fmaf(v0.y, sr[i].y,
                 fmaf(v0.z, sr[i].z, fmaf(v0.w, sr[i].w, p0))));
            p1 = fmaf(v1.x, sr[i + 1].x, fmaf(v1.y, sr[i + 1].y,
                 fmaf(v1.z, sr[i + 1].z, fmaf(v1.w, sr[i + 1].w, p1))));
        }
        float a = p0 + p1;
        a += __shfl_xor_sync(0xffffffffu, a, 1);
        a += __shfl_xor_sync(0xffffffffu, a, 2);
        a += __shfl_xor_sync(0xffffffffu, a, 4);
        if (li8 == 0) Wb[d] = TWO_C * a;
    }
}

// ---------------------------------------------------------------------------
extern "C" void kernel_launch(void* const* d_in, const int* in_sizes, int n_in,
                              void* d_out, int out_size) {
    (void)in_sizes; (void)n_in; (void)out_size;
    rankpool_fused<<<BN, 256>>>((const float*)d_in[0], (float*)d_out);
}

// round 9
// speedup vs baseline: 6.7039x; 1.0403x over previous
#include <cuda_runtime.h>
#include <cuda_bf16.h>
#include <cstdint>

#define BN 256
#define DN 768
#define TN 128
#define NCH 24                /* 32-row chunks                      */
#define SROW 136              /* bf16 elems per staged row (128+8)  */
#define TWO_C 2.0e-5f
#define NIT 4                 /* fixed-point iterations             */

__device__ __forceinline__ uint32_t smem_u32(const void* p) {
    uint32_t a;
    asm("{ .reg .u64 t; cvta.to.shared.u64 t, %1; cvt.u32.u64 %0, t; }" : "=r"(a) : "l"(p));
    return a;
}
__device__ __forceinline__ void cp16(uint32_t dst, const void* src) {
    asm volatile("cp.async.cg.shared.global [%0], [%1], 16;" :: "r"(dst), "l"(src));
}
#define CP_COMMIT() asm volatile("cp.async.commit_group;" ::: "memory")
#define CP_WAIT1()  asm volatile("cp.async.wait_group 1;" ::: "memory")
__device__ __forceinline__ void ldsm4t(uint32_t addr, uint32_t r[4]) {
    asm volatile("ldmatrix.sync.aligned.m8n8.x4.trans.shared.b16 {%0,%1,%2,%3}, [%4];"
                 : "=r"(r[0]), "=r"(r[1]), "=r"(r[2]), "=r"(r[3]) : "r"(addr));
}
__device__ __forceinline__ void mma16816(float c[4], const uint32_t a[4],
                                         uint32_t b0, uint32_t b1) {
    asm volatile("mma.sync.aligned.m16n8k16.row.col.f32.bf16.bf16.f32 "
                 "{%0,%1,%2,%3}, {%4,%5,%6,%7}, {%8,%9}, {%0,%1,%2,%3};"
                 : "+f"(c[0]), "+f"(c[1]), "+f"(c[2]), "+f"(c[3])
                 : "r"(a[0]), "r"(a[1]), "r"(a[2]), "r"(a[3]), "r"(b0), "r"(b1));
}

// ---------------------------------------------------------------------------
// One CTA per batch b. X_b : [D=768][T=128] f32. Woodbury:
//   w = 2C * X * (I + 2C X^T X)^{-1} y,  y = 1..128.
//
// SYMMETRY: M = X^T X. Only the 10 lower-triangle 32x32 blocks are computed:
//   w0:(0,0)+(2,2)  w1:(1,0)  w2:(1,1)+(3,3)  w3:(2,0)
//   w4:(2,1)        w5:(3,0)  w6:(3,1)        w7:(3,2)
// MMA count per k-step: 80 (was 128). The solve reconstructs p = M s from
// the triangle: off-diag block (i,j) gives B*s_j -> rows i (forward) and
// B^T*s_i -> rows j (transpose); partials summed via tmp[8][128].
//
// Phase 1 pipeline (unchanged from R8): 3-deep cp.async ring of 16-row f32
// subs; bf16 double-buffered staging tile; one barrier per 32-row chunk;
// MMA issued before next tile's conversion so tensor work drains under it.
// Phase 3: w = 2C * X s, reverse chunk order (tail still L2-resident).
// ---------------------------------------------------------------------------
__global__ __launch_bounds__(256, 2) void rankpool_fused(const float* __restrict__ X,
                                                         float* __restrict__ W) {
    __shared__ __align__(16) float4 ring[3][512];               // 24 KB f32 ring
    __shared__ __align__(16) __nv_bfloat16 stg[2][32 * SROW];   // 17 KB bf16 tiles
    __shared__ float s_sh[TN];
    __shared__ float tmp[8][TN];                                // 4 KB partials

    const int b = blockIdx.x;
    const int tid = threadIdx.x;
    const int wid = tid >> 5;
    const int lane = tid & 31;
    const int g = lane >> 2, tig = lane & 3;
    const int li = lane & 7, lb3 = (lane >> 3) & 1, lb4 = lane >> 4;

    // block assignment (lower triangle of 4x4 grid of 32x32 blocks)
    int bi0, bj0;
    switch (wid) {
        case 0: bi0 = 0; bj0 = 0; break;
        case 1: bi0 = 1; bj0 = 0; break;
        case 2: bi0 = 1; bj0 = 1; break;
        case 3: bi0 = 2; bj0 = 0; break;
        case 4: bi0 = 2; bj0 = 1; break;
        case 5: bi0 = 3; bj0 = 0; break;
        case 6: bi0 = 3; bj0 = 1; break;
        default: bi0 = 3; bj0 = 2; break;
    }
    const bool two = (wid == 0) | (wid == 2);   // second (diagonal) block
    const int bi1 = (wid == 0) ? 2 : 3;         // (2,2) or (3,3)
    const bool offd = (bi0 != bj0);

    const float4* __restrict__ Xb4 =
        reinterpret_cast<const float4*>(X + (size_t)b * DN * TN);

    float acc0[2][4][4], acc1[2][4][4];
#pragma unroll
    for (int mt = 0; mt < 2; ++mt)
#pragma unroll
        for (int nt = 0; nt < 4; ++nt)
#pragma unroll
            for (int c = 0; c < 4; ++c) { acc0[mt][nt][c] = 0.f; acc1[mt][nt][c] = 0.f; }

    // lane-dependent ldmatrix byte offsets (add (row0)*2 / (col0)*2 per block)
    const uint32_t a_lane = (uint32_t)(((lb4 * 8 + li) * SROW + lb3 * 8) * 2);
    const uint32_t b_lane = (uint32_t)(((lb3 * 8 + li) * SROW + lb4 * 8) * 2);

    const uint32_t stg_addr0 = smem_u32(&stg[0][0]);
    const uint32_t ring_addr = smem_u32(&ring[0][0]);

    const int dl0 = tid >> 5;              // d-row for f = tid       (0..7)
    const int dl1 = (tid + 256) >> 5;      // d-row for f = tid+256   (8..15)
    const int t0 = (tid & 31) * 4;

    auto convert_sub = [&](int slot, int buf, int rbase) {
        const float4* st = ring[slot];
        const float4 v0 = st[tid];
        const float4 v1 = st[tid + 256];
        __nv_bfloat162 p0 = __floats2bfloat162_rn(v0.x, v0.y);
        __nv_bfloat162 p1 = __floats2bfloat162_rn(v0.z, v0.w);
        uint2 u0; u0.x = *reinterpret_cast<const uint32_t*>(&p0);
        u0.y = *reinterpret_cast<const uint32_t*>(&p1);
        *reinterpret_cast<uint2*>(&stg[buf][(rbase + dl0) * SROW + t0]) = u0;
        __nv_bfloat162 q0 = __floats2bfloat162_rn(v1.x, v1.y);
        __nv_bfloat162 q1 = __floats2bfloat162_rn(v1.z, v1.w);
        uint2 u1; u1.x = *reinterpret_cast<const uint32_t*>(&q0);
        u1.y = *reinterpret_cast<const uint32_t*>(&q1);
        *reinterpret_cast<uint2*>(&stg[buf][(rbase + dl1) * SROW + t0]) = u1;
    };
    auto issue_sub = [&](int s) {
        const uint32_t dst = ring_addr + (uint32_t)((s % 3) * 512 + tid) * 16u;
        cp16(dst, Xb4 + s * 512 + tid);
        cp16(dst + 256 * 16, Xb4 + s * 512 + tid + 256);
    };
    // MMA one 32x32 block: rows bi*32.., cols bj*32.. from tile at kbase
    auto mma_block = [&](uint32_t kbase, int bi, int bj, float A[2][4][4]) {
        uint32_t aF0[4], aF1[4], bF0[4], bF1[4];
        ldsm4t(kbase + a_lane + (uint32_t)((bi * 32) * 2), aF0);
        ldsm4t(kbase + a_lane + (uint32_t)((bi * 32 + 16) * 2), aF1);
        ldsm4t(kbase + b_lane + (uint32_t)((bj * 32) * 2), bF0);
        ldsm4t(kbase + b_lane + (uint32_t)((bj * 32 + 16) * 2), bF1);
        mma16816(A[0][0], aF0, bF0[0], bF0[1]);
        mma16816(A[0][1], aF0, bF0[2], bF0[3]);
        mma16816(A[0][2], aF0, bF1[0], bF1[1]);
        mma16816(A[0][3], aF0, bF1[2], bF1[3]);
        mma16816(A[1][0], aF1, bF0[0], bF0[1]);
        mma16816(A[1][1], aF1, bF0[2], bF0[3]);
        mma16816(A[1][2], aF1, bF1[0], bF1[1]);
        mma16816(A[1][3], aF1, bF1[2], bF1[3]);
    };

    // ---------------- Phase 1: Gram ----------------
#pragma unroll
    for (int s = 0; s < 3; ++s) { issue_sub(s); CP_COMMIT(); }
    CP_WAIT1();
    convert_sub(0, 0, 0);
    convert_sub(1, 0, 16);
    issue_sub(3); CP_COMMIT();
    issue_sub(4); CP_COMMIT();

    for (int c = 0; c < NCH; ++c) {
        const uint32_t mybuf = stg_addr0 + (uint32_t)((c & 1) * 32 * SROW * 2);
        __syncthreads();   // stg[c&1] visible; stg[(c+1)&1] free

#pragma unroll
        for (int ks = 0; ks < 2; ++ks) {
            const uint32_t kbase = mybuf + (uint32_t)(ks * 16 * SROW * 2);
            mma_block(kbase, bi0, bj0, acc0);
            if (two) mma_block(kbase, bi1, bi1, acc1);
        }

        if (c + 1 < NCH) {
            CP_WAIT1();
            convert_sub((2 * c + 2) % 3, (c + 1) & 1, 0);
            convert_sub((2 * c + 3) % 3, (c + 1) & 1, 16);
            if (2 * c + 5 < 2 * NCH) issue_sub(2 * c + 5);
            CP_COMMIT();
            if (2 * c + 6 < 2 * NCH) issue_sub(2 * c + 6);
            CP_COMMIT();
        }
    }

    // ---------------- Phase 2: fixed-point solve ----------------
    // fragment: acc[mt][nt][2h+q] = block(row mt*16+h*8+g, col nt*8+2tig+q)
    reinterpret_cast<float4*>(&tmp[0][0])[tid] = make_float4(0.f, 0.f, 0.f, 0.f);
    if (tid < TN) s_sh[tid] = (float)(tid + 1);
    __syncthreads();

    for (int it = 0; it < NIT; ++it) {
        // forward: rows bi*32.., weights s[bj*32..]
        float pf0[2][2] = {{0.f, 0.f}, {0.f, 0.f}};
        float pf1[2][2] = {{0.f, 0.f}, {0.f, 0.f}};
#pragma unroll
        for (int nt = 0; nt < 4; ++nt) {
            const float2 sv0 =
                *reinterpret_cast<const float2*>(&s_sh[bj0 * 32 + nt * 8 + 2 * tig]);
#pragma unroll
            for (int mt = 0; mt < 2; ++mt) {
                pf0[mt][0] = fmaf(acc0[mt][nt][0], sv0.x, fmaf(acc0[mt][nt][1], sv0.y, pf0[mt][0]));
                pf0[mt][1] = fmaf(acc0[mt][nt][2], sv0.x, fmaf(acc0[mt][nt][3], sv0.y, pf0[mt][1]));
            }
            if (two) {
                const float2 sv1 =
                    *reinterpret_cast<const float2*>(&s_sh[bi1 * 32 + nt * 8 + 2 * tig]);
#pragma unroll
                for (int mt = 0; mt < 2; ++mt) {
                    pf1[mt][0] = fmaf(acc1[mt][nt][0], sv1.x, fmaf(acc1[mt][nt][1], sv1.y, pf1[mt][0]));
                    pf1[mt][1] = fmaf(acc1[mt][nt][2], sv1.x, fmaf(acc1[mt][nt][3], sv1.y, pf1[mt][1]));
                }
            }
        }
#pragma unroll
        for (int mt = 0; mt < 2; ++mt)
#pragma unroll
            for (int h = 0; h < 2; ++h) {
                pf0[mt][h] += __shfl_xor_sync(0xffffffffu, pf0[mt][h], 1);
                pf0[mt][h] += __shfl_xor_sync(0xffffffffu, pf0[mt][h], 2);
                if (two) {
                    pf1[mt][h] += __shfl_xor_sync(0xffffffffu, pf1[mt][h], 1);
                    pf1[mt][h] += __shfl_xor_sync(0xffffffffu, pf1[mt][h], 2);
                }
            }

        // transpose: cols bj0*32.., weights s[bi0*32..] (off-diag blocks only)
        float pt[4][2] = {{0.f,0.f},{0.f,0.f},{0.f,0.f},{0.f,0.f}};
        if (offd) {
#pragma unroll
            for (int mt = 0; mt < 2; ++mt)
#pragma unroll
                for (int h = 0; h < 2; ++h) {
                    const float sm = s_sh[bi0 * 32 + mt * 16 + h * 8 + g];
#pragma unroll
                    for (int nt = 0; nt < 4; ++nt) {
                        pt[nt][0] = fmaf(acc0[mt][nt][2 * h + 0], sm, pt[nt][0]);
                        pt[nt][1] = fmaf(acc0[mt][nt][2 * h + 1], sm, pt[nt][1]);
                    }
                }
#pragma unroll
            for (int nt = 0; nt < 4; ++nt)
#pragma unroll
                for (int q = 0; q < 2; ++q) {
                    pt[nt][q] += __shfl_xor_sync(0xffffffffu, pt[nt][q], 4);
                    pt[nt][q] += __shfl_xor_sync(0xffffffffu, pt[nt][q], 8);
                    pt[nt][q] += __shfl_xor_sync(0xffffffffu, pt[nt][q], 16);
                }
        }

        if (tig == 0) {
#pragma unroll
            for (int mt = 0; mt < 2; ++mt)
#pragma unroll
                for (int h = 0; h < 2; ++h) {
                    tmp[wid][bi0 * 32 + mt * 16 + h * 8 + g] = pf0[mt][h];
                    if (two) tmp[wid][bi1 * 32 + mt * 16 + h * 8 + g] = pf1[mt][h];
                }
        }
        if (offd && lane < 4) {   // g==0 lanes; tig == lane
#pragma unroll
            for (int nt = 0; nt < 4; ++nt) {
                tmp[wid][bj0 * 32 + nt * 8 + 2 * tig + 0] = pt[nt][0];
                tmp[wid][bj0 * 32 + nt * 8 + 2 * tig + 1] = pt[nt][1];
            }
        }
        __syncthreads();
        if (tid < TN) {
            float acc = 0.f;
#pragma unroll
            for (int w = 0; w < 8; ++w) acc += tmp[w][tid];
            s_sh[tid] = (float)(tid + 1) - TWO_C * acc;
        }
        __syncthreads();
    }

    // ---------------- Phase 3: epilogue w = 2C * X s (reverse order) -----
    const int li8 = lane & 7, rsub = lane >> 3;
    float4 sr[4];
    {
        const float4* s4 = reinterpret_cast<const float4*>(s_sh);
#pragma unroll
        for (int i = 0; i < 4; ++i) sr[i] = s4[i * 8 + li8];
    }
    float* Wb = W + (size_t)b * DN;
#pragma unroll 2
    for (int r = DN / 32 - 1; r >= 0; --r) {
        const int d = r * 32 + wid * 4 + rsub;
        const float4* row = Xb4 + (size_t)d * 32;
        float p0 = 0.f, p1 = 0.f;
#pragma unroll
        for (int i = 0; i < 4; i += 2) {
            const float4 v0 = row[i * 8 + li8];
            const float4 v1 = row[(i + 1) * 8 + li8];
            p0 = fmaf(v0.x, sr[i].x, fmaf(v0.y, sr[i].y,
                 fmaf(v0.z, sr[i].z, fmaf(v0.w, sr[i].w, p0))));
            p1 = fmaf(v1.x, sr[i + 1].x, fmaf(v1.y, sr[i + 1].y,
                 fmaf(v1.z, sr[i + 1].z, fmaf(v1.w, sr[i + 1].w, p1))));
        }
        float a = p0 + p1;
        a += __shfl_xor_sync(0xffffffffu, a, 1);
        a += __shfl_xor_sync(0xffffffffu, a, 2);
        a += __shfl_xor_sync(0xffffffffu, a, 4);
        if (li8 == 0) Wb[d] = TWO_C * a;
    }
}

// ---------------------------------------------------------------------------
extern "C" void kernel_launch(void* const* d_in, const int* in_sizes, int n_in,
                              void* d_out, int out_size) {
    (void)in_sizes; (void)n_in; (void)out_size;
    rankpool_fused<<<BN, 256>>>((const float*)d_in[0], (float*)d_out);
}

// round 10
// speedup vs baseline: 6.7523x; 1.0072x over previous
#include <cuda_runtime.h>
#include <cuda_bf16.h>
#include <cstdint>

#define BN 256
#define DN 768
#define TN 128
#define NCH 24                /* 32-row chunks                      */
#define NSUB 48               /* 16-row f32 subs                    */
#define TWO_C 2.0e-5f
#define NIT 4                 /* fixed-point iterations             */

__device__ __forceinline__ uint32_t smem_u32(const void* p) {
    uint32_t a;
    asm("{ .reg .u64 t; cvta.to.shared.u64 t, %1; cvt.u32.u64 %0, t; }" : "=r"(a) : "l"(p));
    return a;
}
__device__ __forceinline__ void cp16(uint32_t dst, const void* src) {
    asm volatile("cp.async.cg.shared.global [%0], [%1], 16;" :: "r"(dst), "l"(src));
}
#define CP_COMMIT() asm volatile("cp.async.commit_group;" ::: "memory")
#define CP_WAIT3()  asm volatile("cp.async.wait_group 3;" ::: "memory")
#define CP_WAIT0()  asm volatile("cp.async.wait_group 0;" ::: "memory")
__device__ __forceinline__ void ldsm4t(uint32_t addr, uint32_t r[4]) {
    asm volatile("ldmatrix.sync.aligned.m8n8.x4.trans.shared.b16 {%0,%1,%2,%3}, [%4];"
                 : "=r"(r[0]), "=r"(r[1]), "=r"(r[2]), "=r"(r[3]) : "r"(addr));
}
__device__ __forceinline__ void mma16816(float c[4], const uint32_t a[4],
                                         uint32_t b0, uint32_t b1) {
    asm volatile("mma.sync.aligned.m16n8k16.row.col.f32.bf16.bf16.f32 "
                 "{%0,%1,%2,%3}, {%4,%5,%6,%7}, {%8,%9}, {%0,%1,%2,%3};"
                 : "+f"(c[0]), "+f"(c[1]), "+f"(c[2]), "+f"(c[3])
                 : "r"(a[0]), "r"(a[1]), "r"(a[2]), "r"(a[3]), "r"(b0), "r"(b1));
}

// ---------------------------------------------------------------------------
// One CTA per batch b. X_b : [D=768][T=128] f32. Woodbury:
//   w = 2C * X * (I + 2C X^T X)^{-1} y,  y = 1..128.
//
// SMEM pool (48 KB exactly):
//   [0, 32K)   4-slot f32 ring (16-row subs, 8 KB each)   | aliased after
//   [32K,48K)  2 bf16 staging tiles, 32 rows x 256 B,     | gram: tmp[8][128]
//              XOR-16B swizzled (conflict-free ldmatrix)  | at 0, s_sh at 4K
//
// DRAM feed discipline (the R10 fix): per-SUB cadence with wait_group 3 on a
// 4-deep ring -> 3..4 groups (24-32 KB/CTA) permanently outstanding, vs the
// old wait_group-1-per-chunk which drained to 8 KB (measured 2.94 TB/s).
// Unconditional commits keep group accounting uniform at the tail.
//
// Gram uses symmetry: 10 lower-triangle 32x32 blocks across 8 warps
// (w0:(0,0)+(2,2), w2:(1,1)+(3,3), others one off-diag block each).
// Solve reconstructs p = M s from the triangle (forward + transposed parts).
// Epilogue: w = 2C * X s in reverse chunk order (tail still L2-resident).
// ---------------------------------------------------------------------------
__global__ __launch_bounds__(256, 2) void rankpool_fused(const float* __restrict__ X,
                                                         float* __restrict__ W) {
    __shared__ __align__(1024) char pool[49152];
    float4* ring = reinterpret_cast<float4*>(pool);           // [4][512]
    char* stgp = pool + 32768;                                 // 2 x 8192 B

    const int b = blockIdx.x;
    const int tid = threadIdx.x;
    const int wid = tid >> 5;
    const int lane = tid & 31;
    const int g = lane >> 2, tig = lane & 3;
    const int li = lane & 7, lb3 = (lane >> 3) & 1, lb4 = lane >> 4;

    int bi0, bj0;
    switch (wid) {
        case 0: bi0 = 0; bj0 = 0; break;
        case 1: bi0 = 1; bj0 = 0; break;
        case 2: bi0 = 1; bj0 = 1; break;
        case 3: bi0 = 2; bj0 = 0; break;
        case 4: bi0 = 2; bj0 = 1; break;
        case 5: bi0 = 3; bj0 = 0; break;
        case 6: bi0 = 3; bj0 = 1; break;
        default: bi0 = 3; bj0 = 2; break;
    }
    const bool two = (wid == 0) | (wid == 2);
    const int bi1 = (wid == 0) ? 2 : 3;
    const bool offd = (bi0 != bj0);

    const float4* __restrict__ Xb4 =
        reinterpret_cast<const float4*>(X + (size_t)b * DN * TN);

    float acc0[2][4][4], acc1[2][4][4];
#pragma unroll
    for (int mt = 0; mt < 2; ++mt)
#pragma unroll
        for (int nt = 0; nt < 4; ++nt)
#pragma unroll
            for (int c = 0; c < 4; ++c) { acc0[mt][nt][c] = 0.f; acc1[mt][nt][c] = 0.f; }

    // ldmatrix lane row bases (swizzle XOR uses row&7 == li for both A and B)
    const uint32_t stg_addr = smem_u32(stgp);
    const uint32_t ring_addr = smem_u32(pool);
    const uint32_t arow = (uint32_t)((lb4 * 8 + li) * 256);
    const uint32_t brow = (uint32_t)((lb3 * 8 + li) * 256);
    const uint32_t li16 = (uint32_t)(li * 16);
    const uint32_t a_c16 = (uint32_t)(lb3 * 16);   // column byte within block
    const uint32_t b_c16 = (uint32_t)(lb4 * 16);

    // converter store mapping: warp writes one row; swizzled 16B segments
    const int seg = (tid & 31) >> 1;
    const int low = (tid & 1) * 8;
    const int dl = tid >> 5;                       // 0..7 within each half

    auto convert_sub = [&](int slot, int buf, int rbase) {
        const float4 v0 = ring[slot * 512 + tid];
        const float4 v1 = ring[slot * 512 + tid + 256];
        char* base = stgp + buf * 8192;
        {
            const int row = rbase + dl;
            __nv_bfloat162 p0 = __floats2bfloat162_rn(v0.x, v0.y);
            __nv_bfloat162 p1 = __floats2bfloat162_rn(v0.z, v0.w);
            uint2 u; u.x = *reinterpret_cast<const uint32_t*>(&p0);
            u.y = *reinterpret_cast<const uint32_t*>(&p1);
            *reinterpret_cast<uint2*>(base + row * 256 +
                ((seg * 16) ^ ((row & 7) * 16)) + low) = u;
        }
        {
            const int row = rbase + 8 + dl;
            __nv_bfloat162 p0 = __floats2bfloat162_rn(v1.x, v1.y);
            __nv_bfloat162 p1 = __floats2bfloat162_rn(v1.z, v1.w);
            uint2 u; u.x = *reinterpret_cast<const uint32_t*>(&p0);
            u.y = *reinterpret_cast<const uint32_t*>(&p1);
            *reinterpret_cast<uint2*>(base + row * 256 +
                ((seg * 16) ^ ((row & 7) * 16)) + low) = u;
        }
    };
    auto issue_sub = [&](int s) {
        const uint32_t dst = ring_addr + (uint32_t)((s & 3) * 512 + tid) * 16u;
        cp16(dst, Xb4 + s * 512 + tid);
        cp16(dst + 256 * 16, Xb4 + s * 512 + tid + 256);
    };
    auto mma_block = [&](uint32_t kbase, int bi, int bj, float A[2][4][4]) {
        uint32_t aF0[4], aF1[4], bF0[4], bF1[4];
        const uint32_t ca = (uint32_t)(bi * 64);
        const uint32_t cb = (uint32_t)(bj * 64);
        ldsm4t(kbase + arow + (((ca + 0) + a_c16) ^ li16), aF0);
        ldsm4t(kbase + arow + (((ca + 32) + a_c16) ^ li16), aF1);
        ldsm4t(kbase + brow + (((cb + 0) + b_c16) ^ li16), bF0);
        ldsm4t(kbase + brow + (((cb + 32) + b_c16) ^ li16), bF1);
        mma16816(A[0][0], aF0, bF0[0], bF0[1]);
        mma16816(A[0][1], aF0, bF0[2], bF0[3]);
        mma16816(A[0][2], aF0, bF1[0], bF1[1]);
        mma16816(A[0][3], aF0, bF1[2], bF1[3]);
        mma16816(A[1][0], aF1, bF0[0], bF0[1]);
        mma16816(A[1][1], aF1, bF0[2], bF0[3]);
        mma16816(A[1][2], aF1, bF1[0], bF1[1]);
        mma16816(A[1][3], aF1, bF1[2], bF1[3]);
    };

    // ---------------- Phase 1: Gram ----------------
#pragma unroll
    for (int s = 0; s < 4; ++s) { issue_sub(s); CP_COMMIT(); }
    CP_WAIT3(); convert_sub(0, 0, 0);  issue_sub(4); CP_COMMIT();
    CP_WAIT3(); convert_sub(1, 0, 16); issue_sub(5); CP_COMMIT();

    for (int c = 0; c < NCH; ++c) {
        const uint32_t mybuf = stg_addr + (uint32_t)((c & 1) * 8192);
        __syncthreads();   // stg[c&1] fully written; stg[(c+1)&1] free

#pragma unroll
        for (int ks = 0; ks < 2; ++ks) {
            const uint32_t kbase = mybuf + (uint32_t)(ks * 4096);
            mma_block(kbase, bi0, bj0, acc0);
            if (two) mma_block(kbase, bi1, bi1, acc1);
        }

        if (c + 1 < NCH) {
            CP_WAIT3();                      // sub 2c+2 arrived (3 left pending)
            convert_sub((2 * c + 2) & 3, (c + 1) & 1, 0);
            if (2 * c + 6 < NSUB) issue_sub(2 * c + 6);
            CP_COMMIT();
            CP_WAIT3();                      // sub 2c+3 arrived
            convert_sub((2 * c + 3) & 3, (c + 1) & 1, 16);
            if (2 * c + 7 < NSUB) issue_sub(2 * c + 7);
            CP_COMMIT();
        }
    }
    CP_WAIT0();
    __syncthreads();                         // ring dead -> alias tmp/s_sh

    // ---------------- Phase 2: fixed-point solve ----------------
    float (*tmp)[TN] = reinterpret_cast<float (*)[TN]>(pool);      // 4 KB
    float* s_sh = reinterpret_cast<float*>(pool + 4096);
    reinterpret_cast<float4*>(&tmp[0][0])[tid] = make_float4(0.f, 0.f, 0.f, 0.f);
    if (tid < TN) s_sh[tid] = (float)(tid + 1);
    __syncthreads();

    for (int it = 0; it < NIT; ++it) {
        float pf0[2][2] = {{0.f, 0.f}, {0.f, 0.f}};
        float pf1[2][2] = {{0.f, 0.f}, {0.f, 0.f}};
#pragma unroll
        for (int nt = 0; nt < 4; ++nt) {
            const float2 sv0 =
                *reinterpret_cast<const float2*>(&s_sh[bj0 * 32 + nt * 8 + 2 * tig]);
#pragma unroll
            for (int mt = 0; mt < 2; ++mt) {
                pf0[mt][0] = fmaf(acc0[mt][nt][0], sv0.x, fmaf(acc0[mt][nt][1], sv0.y, pf0[mt][0]));
                pf0[mt][1] = fmaf(acc0[mt][nt][2], sv0.x, fmaf(acc0[mt][nt][3], sv0.y, pf0[mt][1]));
            }
            if (two) {
                const float2 sv1 =
                    *reinterpret_cast<const float2*>(&s_sh[bi1 * 32 + nt * 8 + 2 * tig]);
#pragma unroll
                for (int mt = 0; mt < 2; ++mt) {
                    pf1[mt][0] = fmaf(acc1[mt][nt][0], sv1.x, fmaf(acc1[mt][nt][1], sv1.y, pf1[mt][0]));
                    pf1[mt][1] = fmaf(acc1[mt][nt][2], sv1.x, fmaf(acc1[mt][nt][3], sv1.y, pf1[mt][1]));
                }
            }
        }
#pragma unroll
        for (int mt = 0; mt < 2; ++mt)
#pragma unroll
            for (int h = 0; h < 2; ++h) {
                pf0[mt][h] += __shfl_xor_sync(0xffffffffu, pf0[mt][h], 1);
                pf0[mt][h] += __shfl_xor_sync(0xffffffffu, pf0[mt][h], 2);
                if (two) {
                    pf1[mt][h] += __shfl_xor_sync(0xffffffffu, pf1[mt][h], 1);
                    pf1[mt][h] += __shfl_xor_sync(0xffffffffu, pf1[mt][h], 2);
                }
            }

        float pt[4][2] = {{0.f,0.f},{0.f,0.f},{0.f,0.f},{0.f,0.f}};
        if (offd) {
#pragma unroll
            for (int mt = 0; mt < 2; ++mt)
#pragma unroll
                for (int h = 0; h < 2; ++h) {
                    const float sm = s_sh[bi0 * 32 + mt * 16 + h * 8 + g];
#pragma unroll
                    for (int nt = 0; nt < 4; ++nt) {
                        pt[nt][0] = fmaf(acc0[mt][nt][2 * h + 0], sm, pt[nt][0]);
                        pt[nt][1] = fmaf(acc0[mt][nt][2 * h + 1], sm, pt[nt][1]);
                    }
                }
#pragma unroll
            for (int nt = 0; nt < 4; ++nt)
#pragma unroll
                for (int q = 0; q < 2; ++q) {
                    pt[nt][q] += __shfl_xor_sync(0xffffffffu, pt[nt][q], 4);
                    pt[nt][q] += __shfl_xor_sync(0xffffffffu, pt[nt][q], 8);
                    pt[nt][q] += __shfl_xor_sync(0xffffffffu, pt[nt][q], 16);
                }
        }

        if (tig == 0) {
#pragma unroll
            for (int mt = 0; mt < 2; ++mt)
#pragma unroll
                for (int h = 0; h < 2; ++h) {
                    tmp[wid][bi0 * 32 + mt * 16 + h * 8 + g] = pf0[mt][h];
                    if (two) tmp[wid][bi1 * 32 + mt * 16 + h * 8 + g] = pf1[mt][h];
                }
        }
        if (offd && lane < 4) {
#pragma unroll
            for (int nt = 0; nt < 4; ++nt) {
                tmp[wid][bj0 * 32 + nt * 8 + 2 * tig + 0] = pt[nt][0];
                tmp[wid][bj0 * 32 + nt * 8 + 2 * tig + 1] = pt[nt][1];
            }
        }
        __syncthreads();
        if (tid < TN) {
            float acc = 0.f;
#pragma unroll
            for (int w = 0; w < 8; ++w) acc += tmp[w][tid];
            s_sh[tid] = (float)(tid + 1) - TWO_C * acc;
        }
        __syncthreads();
    }

    // ---------------- Phase 3: epilogue w = 2C * X s (reverse order) -----
    const int li8 = lane & 7, rsub = lane >> 3;
    float4 sr[4];
    {
        const float4* s4 = reinterpret_cast<const float4*>(s_sh);
#pragma unroll
        for (int i = 0; i < 4; ++i) sr[i] = s4[i * 8 + li8];
    }
    float* Wb = W + (size_t)b * DN;
#pragma unroll 2
    for (int r = DN / 32 - 1; r >= 0; --r) {
        const int d = r * 32 + wid * 4 + rsub;
        const float4* row = Xb4 + (size_t)d * 32;
        float p0 = 0.f, p1 = 0.f;
#pragma unroll
        for (int i = 0; i < 4; i += 2) {
            const float4 v0 = row[i * 8 + li8];
            const float4 v1 = row[(i + 1) * 8 + li8];
            p0 = fmaf(v0.x, sr[i].x, fmaf(v0.y, sr[i].y,
                 fmaf(v0.z, sr[i].z, fmaf(v0.w, sr[i].w, p0))));
            p1 = fmaf(v1.x, sr[i + 1].x, fmaf(v1.y, sr[i + 1].y,
                 fmaf(v1.z, sr[i + 1].z, fmaf(v1.w, sr[i + 1].w, p1))));
        }
        float a = p0 + p1;
        a += __shfl_xor_sync(0xffffffffu, a, 1);
        a += __shfl_xor_sync(0xffffffffu, a, 2);
        a += __shfl_xor_sync(0xffffffffu, a, 4);
        if (li8 == 0) Wb[d] = TWO_C * a;
    }
}

// ---------------------------------------------------------------------------
extern "C" void kernel_launch(void* const* d_in, const int* in_sizes, int n_in,
                              void* d_out, int out_size) {
    (void)in_sizes; (void)n_in; (void)out_size;
    rankpool_fused<<<BN, 256>>>((const float*)d_in[0], (float*)d_out);
}